// round 9
// baseline (speedup 1.0000x reference)
#include <cuda_runtime.h>
#include <cuda_bf16.h>
#include <cstdint>
#include <cstddef>

#define HID 128
#define GSZ 512
#define BATCH 1024
#define TLEN 512
#define DIN 12
#define KP0 144
#define KP1 128
#define SRR 96
#define BT 8
#define NBLK 128
#define MROWS (TLEN*BATCH)
#define AS 264
#define BSTR 392

typedef unsigned long long ull;

__device__ float g_W0T[KP0*GSZ];
__device__ float g_W1T[KP1*GSZ];
__device__ float g_bias0[GSZ];
__device__ float g_bias1[GSZ];
__device__ __nv_bfloat16 g_h1s[(size_t)MROWS*256];   // [row][hi128|lo128]
__device__ __nv_bfloat16 g_BE[GSZ*384];              // [n][384] = wh|wh|wl
__device__ float g_xp1[(size_t)MROWS*GSZ];
__device__ float g_h2[BATCH*HID];

__device__ __forceinline__ ull dup2(float x){ull d;asm("mov.b64 %0,{%1,%1};":"=l"(d):"f"(x));return d;}
__device__ __forceinline__ ull pk2(float x,float y){ull d;asm("mov.b64 %0,{%1,%2};":"=l"(d):"f"(x),"f"(y));return d;}
__device__ __forceinline__ ull fma2(ull a,ull b,ull c){ull d;asm("fma.rn.f32x2 %0,%1,%2,%3;":"=l"(d):"l"(a),"l"(b),"l"(c));return d;}
__device__ __forceinline__ float2 unp(ull v){float2 r;asm("mov.b64 {%0,%1},%2;":"=f"(r.x),"=f"(r.y):"l"(v));return r;}
__device__ __forceinline__ float sigm(float x){return __fdividef(1.0f,1.0f+__expf(-x));}
__device__ __forceinline__ float tanh_f(float x){return __fdividef(2.0f,1.0f+__expf(-2.0f*x))-1.0f;}

// one weight value (this thread's column) x 8 batch rows -> 4 f32x2 accs
#define FMA_ROW1(WF,KIDX) do{ \
    ull wd=dup2(WF); \
    ulonglong2 vA=*(const ulonglong2*)&v_s[(KIDX)*12]; \
    ulonglong2 vB=*(const ulonglong2*)&v_s[(KIDX)*12+4]; \
    a0=fma2(wd,vA.x,a0); a1=fma2(wd,vA.y,a1); \
    a2=fma2(wd,vB.x,a2); a3=fma2(wd,vB.y,a3); }while(0)

#define MMA(d,a,b0,b1) \
    asm volatile("mma.sync.aligned.m16n8k16.row.col.f32.bf16.bf16.f32 " \
        "{%0,%1,%2,%3},{%4,%5,%6,%7},{%8,%9},{%0,%1,%2,%3};" \
        : "+f"((d)[0]),"+f"((d)[1]),"+f"((d)[2]),"+f"((d)[3]) \
        : "r"((a)[0]),"r"((a)[1]),"r"((a)[2]),"r"((a)[3]),"r"(b0),"r"(b1))

__global__ void prep_kernel(const float* __restrict__ Wih0,const float* __restrict__ Whh0,
                            const float* __restrict__ bih0,const float* __restrict__ bhh0,
                            const float* __restrict__ Wih1,const float* __restrict__ Whh1,
                            const float* __restrict__ bih1,const float* __restrict__ bhh1){
    int i = blockIdx.x*blockDim.x + threadIdx.x;
    const int S0=KP0*GSZ, S1=S0+KP1*GSZ, S2=S1+GSZ, S3=S2+GSZ, S4=S3+GSZ*384;
    if(i<S0){
        int k=i/GSZ, j=i%GSZ; float v=0.f;
        if(k<DIN) v=Wih0[j*DIN+k]; else if(k<DIN+HID) v=Whh0[j*HID+(k-DIN)];
        g_W0T[i]=v;
    }else if(i<S1){
        int i2=i-S0; int k=i2/GSZ, j=i2%GSZ;
        g_W1T[i2]=Whh1[j*HID+k];
    }else if(i<S2){ int j=i-S1; g_bias0[j]=bih0[j]+bhh0[j]; }
    else if(i<S3){ int j=i-S2; g_bias1[j]=bih1[j]+bhh1[j]; }
    else if(i<S4){
        int i2=i-S3; int n=i2/384, kp=i2%384, k=kp&127;
        float w=Wih1[n*HID+k];
        __nv_bfloat16 hi=__float2bfloat16(w);
        g_BE[i2] = (kp<256)? hi : __float2bfloat16(w-__bfloat162float(hi));
    }
}

// xp1 = h1(split bf16) @ W_ih1^T + b1 via mma.sync; A and B tiles both in smem.
__global__ void __launch_bounds__(256,1) xp_gemm_kernel(){
    extern __shared__ __nv_bfloat16 sh[];
    __nv_bfloat16* As = sh;                // [128][AS]
    __nv_bfloat16* Bs = sh + 128*AS;       // [128][BSTR]
    int tid=threadIdx.x, wid=tid>>5, lane=tid&31;
    int g=lane>>2, t=lane&3;
    size_t mbase=(size_t)blockIdx.x*128;
    int ny=blockIdx.y;
    {
        const float4* src=(const float4*)(g_h1s + mbase*256);
        for(int i=tid;i<4096;i+=256){
            int r=i>>5, c=i&31;
            *(float4*)(As + r*AS + c*8)=src[r*32+c];
        }
        const float4* bsrc=(const float4*)(g_BE + (size_t)ny*128*384);
        for(int i=tid;i<6144;i+=256){
            int n=i/48, kq=i%48;
            *(float4*)(Bs + n*BSTR + kq*8)=bsrc[i];
        }
    }
    __syncthreads();
    int nl0=(wid>>2)*64;     // local n base (0 or 64)
    int m0=(wid&3)*32;
    float acc[2][8][4];
#pragma unroll
    for(int mi=0;mi<2;mi++)
#pragma unroll
        for(int ni=0;ni<8;ni++)
#pragma unroll
            for(int q=0;q<4;q++) acc[mi][ni][q]=0.f;
#pragma unroll 1
    for(int kc=0;kc<24;kc++){
        int ks=(kc<8)?kc*16:(kc<16)?(128+(kc-8)*16):((kc-16)*16);
        int kb=kc*16;
        uint32_t a[2][4];
#pragma unroll
        for(int mi=0;mi<2;mi++){
            const __nv_bfloat16* ap=As+(m0+mi*16)*AS+ks;
            a[mi][0]=*(const uint32_t*)(ap+g*AS+2*t);
            a[mi][1]=*(const uint32_t*)(ap+(g+8)*AS+2*t);
            a[mi][2]=*(const uint32_t*)(ap+g*AS+2*t+8);
            a[mi][3]=*(const uint32_t*)(ap+(g+8)*AS+2*t+8);
        }
#pragma unroll
        for(int ni=0;ni<8;ni++){
            const __nv_bfloat16* bp=Bs+(nl0+ni*8+g)*BSTR+kb;
            uint32_t b0=*(const uint32_t*)(bp+2*t);
            uint32_t b1=*(const uint32_t*)(bp+2*t+8);
            MMA(acc[0][ni],a[0],b0,b1);
            MMA(acc[1][ni],a[1],b0,b1);
        }
    }
#pragma unroll
    for(int mi=0;mi<2;mi++)
#pragma unroll
        for(int ni=0;ni<8;ni++){
            int col=ny*128+nl0+ni*8+2*t;
            float bx=g_bias1[col], by=g_bias1[col+1];
            size_t r0=mbase+m0+mi*16+g;
            *(float2*)&g_xp1[r0*GSZ+col]     = make_float2(acc[mi][ni][0]+bx, acc[mi][ni][1]+by);
            *(float2*)&g_xp1[(r0+8)*GSZ+col] = make_float2(acc[mi][ni][2]+bx, acc[mi][ni][3]+by);
        }
}

// fused LSTM scan: 512 threads, 1 gate column per thread, fully weight-resident.
template <int LAYER>
__global__ void __launch_bounds__(512,1) lstm_kernel(const float* __restrict__ x){
    constexpr int KP=(LAYER==0)?KP0:KP1;
    constexpr int PRM=KP-SRR;                 // 48 / 32
    constexpr int KOFF=(LAYER==0)?DIN:0;
    const float* __restrict__ WT=(LAYER==0)?g_W0T:g_W1T;

    extern __shared__ float smem[];
    float* w_s=smem;                 // SRR*512
    float* v_s=w_s+SRR*GSZ;          // KP*12
    float* g_s=v_s+KP*12;            // 8*512

    const int tid=threadIdx.x;
    const int b0=blockIdx.x*BT;
    const int j=tid;
    {
        const float2* src=(const float2*)WT;
        float2* dst=(float2*)w_s;
        for(int i=tid;i<SRR*GSZ/2;i+=512) dst[i]=src[i];
    }
    for(int i=tid;i<KP*12;i+=512) v_s[i]=0.f;

    float pbuf[PRM];
#pragma unroll
    for(int i=0;i<PRM;i++) pbuf[i]=WT[(SRR+i)*GSZ+j];

    ull bjd=0;
    if(LAYER==0) bjd=dup2(g_bias0[j]);

    const int ub=tid>>6, um=tid&63;   // update: batch row, base hidden idx
    float c_r[2]={0.f,0.f};

    for(int t=0;t<TLEN;t++){
        float xstage=0.f; float xpr[8];
        int st_r=0, st_d=0;
        if(LAYER==0){
            if(tid<96){ st_r=tid/12; st_d=tid%12;
                xstage=x[(((size_t)(b0+st_r))*TLEN+t)*DIN+st_d]; }
        }else{
            const float* xpb=g_xp1+(((size_t)t)*BATCH+b0)*GSZ+j;
#pragma unroll
            for(int b=0;b<8;b++) xpr[b]=xpb[(size_t)b*GSZ];
        }
        if(t>0){
#pragma unroll
            for(int q=0;q<2;q++){
                int m=um+64*q;
                float iv=sigm(g_s[ub*GSZ+m]);
                float fv=sigm(g_s[ub*GSZ+128+m]);
                float gv=tanh_f(g_s[ub*GSZ+256+m]);
                float ov=sigm(g_s[ub*GSZ+384+m]);
                float c=fv*c_r[q]+iv*gv; c_r[q]=c;
                float h=ov*tanh_f(c);
                v_s[(KOFF+m)*12+ub]=h;
                if(LAYER==0){
                    size_t row=((size_t)(t-1))*BATCH+b0+ub;
                    __nv_bfloat16 hb=__float2bfloat16(h);
                    g_h1s[row*256+m]=hb;
                    g_h1s[row*256+128+m]=__float2bfloat16(h-__bfloat162float(hb));
                }
            }
        }
        if(LAYER==0){ if(tid<96) v_s[st_d*12+st_r]=xstage; }
        __syncthreads();

        ull a0,a1,a2,a3;
        if(LAYER==0){ a0=bjd;a1=bjd;a2=bjd;a3=bjd; }
        else{
            a0=pk2(xpr[0],xpr[1]); a1=pk2(xpr[2],xpr[3]);
            a2=pk2(xpr[4],xpr[5]); a3=pk2(xpr[6],xpr[7]);
        }
#pragma unroll 4
        for(int k=0;k<SRR;k++) FMA_ROW1(w_s[k*GSZ+j],k);
#pragma unroll
        for(int i=0;i<PRM;i++) FMA_ROW1(pbuf[i],SRR+i);
        {
            float2 u0=unp(a0), u1=unp(a1), u2=unp(a2), u3=unp(a3);
            g_s[0*GSZ+j]=u0.x; g_s[1*GSZ+j]=u0.y;
            g_s[2*GSZ+j]=u1.x; g_s[3*GSZ+j]=u1.y;
            g_s[4*GSZ+j]=u2.x; g_s[5*GSZ+j]=u2.y;
            g_s[6*GSZ+j]=u3.x; g_s[7*GSZ+j]=u3.y;
        }
        __syncthreads();
    }
#pragma unroll
    for(int q=0;q<2;q++){
        int m=um+64*q;
        float iv=sigm(g_s[ub*GSZ+m]);
        float fv=sigm(g_s[ub*GSZ+128+m]);
        float gv=tanh_f(g_s[ub*GSZ+256+m]);
        float ov=sigm(g_s[ub*GSZ+384+m]);
        float c=fv*c_r[q]+iv*gv;
        float h=ov*tanh_f(c);
        if(LAYER==0){
            size_t row=((size_t)(TLEN-1))*BATCH+b0+ub;
            __nv_bfloat16 hb=__float2bfloat16(h);
            g_h1s[row*256+m]=hb;
            g_h1s[row*256+128+m]=__float2bfloat16(h-__bfloat162float(hb));
        }else g_h2[(b0+ub)*HID+m]=h;
    }
}

__global__ void head_kernel(const float* __restrict__ W1,const float* __restrict__ b1,
                            const float* __restrict__ W2,const float* __restrict__ b2,
                            const float* __restrict__ W3,const float* __restrict__ b3,
                            float* __restrict__ out){
    __shared__ float hrow[HID]; __shared__ float z1[64]; __shared__ float z2[32];
    int b=blockIdx.x, tid=threadIdx.x;
    hrow[tid]=g_h2[b*HID+tid];
    hrow[tid+64]=g_h2[b*HID+tid+64];
    __syncthreads();
    {
        float s=b1[tid];
        const float* w=&W1[tid*HID];
#pragma unroll 8
        for(int k=0;k<HID;k++) s+=w[k]*hrow[k];
        z1[tid]=fmaxf(s,0.f);
    }
    __syncthreads();
    if(tid<32){
        float s=b2[tid];
        const float* w=&W2[tid*64];
#pragma unroll 8
        for(int k=0;k<64;k++) s+=w[k]*z1[k];
        z2[tid]=fmaxf(s,0.f);
    }
    __syncthreads();
    if(tid<2){
        float s=b3[tid];
        const float* w=&W3[tid*32];
#pragma unroll
        for(int k=0;k<32;k++) s+=w[k]*z2[k];
        out[b*2+tid]=s;
    }
}

extern "C" void kernel_launch(void* const* d_in, const int* in_sizes, int n_in,
                              void* d_out, int out_size){
    const float* x   =(const float*)d_in[0];
    const float* Wih0=(const float*)d_in[1];
    const float* Whh0=(const float*)d_in[2];
    const float* bih0=(const float*)d_in[3];
    const float* bhh0=(const float*)d_in[4];
    const float* Wih1=(const float*)d_in[5];
    const float* Whh1=(const float*)d_in[6];
    const float* bih1=(const float*)d_in[7];
    const float* bhh1=(const float*)d_in[8];
    const float* W1=(const float*)d_in[9];
    const float* b1=(const float*)d_in[10];
    const float* W2=(const float*)d_in[11];
    const float* b2=(const float*)d_in[12];
    const float* W3=(const float*)d_in[13];
    const float* b3=(const float*)d_in[14];
    float* out=(float*)d_out;

    const int smem0=(SRR*GSZ+KP0*12+8*GSZ)*4;    // 219,904 B
    const int smem1=(SRR*GSZ+KP1*12+8*GSZ)*4;    // 219,136 B
    const int smemg=(128*AS+128*BSTR)*2;          // 167,936 B
    cudaFuncSetAttribute((const void*)lstm_kernel<0>,cudaFuncAttributeMaxDynamicSharedMemorySize,smem0);
    cudaFuncSetAttribute((const void*)lstm_kernel<1>,cudaFuncAttributeMaxDynamicSharedMemorySize,smem1);
    cudaFuncSetAttribute((const void*)xp_gemm_kernel,cudaFuncAttributeMaxDynamicSharedMemorySize,smemg);

    int tot=(KP0+KP1)*GSZ+2*GSZ+GSZ*384;
    prep_kernel<<<(tot+255)/256,256>>>(Wih0,Whh0,bih0,bhh0,Wih1,Whh1,bih1,bhh1);
    lstm_kernel<0><<<NBLK,512,smem0>>>(x);
    xp_gemm_kernel<<<dim3(MROWS/128,4),256,smemg>>>();
    lstm_kernel<1><<<NBLK,512,smem1>>>(nullptr);
    head_kernel<<<BATCH,64>>>(W1,b1,W2,b2,W3,b3,out);
}

// round 10
// speedup vs baseline: 1.2230x; 1.2230x over previous
#include <cuda_runtime.h>
#include <cuda_bf16.h>
#include <cstdint>
#include <cstddef>

#define HID 128
#define GSZ 512
#define BATCH 1024
#define TLEN 512
#define DIN 12
#define KP0 144
#define KP1 128
#define SRR 96
#define BT 8
#define NBLK 128
#define MROWS (TLEN*BATCH)
#define AS 264
#define BSTR 392

typedef unsigned long long ull;

__device__ float g_W0T[KP0*GSZ];
__device__ float g_W1T[KP1*GSZ];
__device__ float g_bias0[GSZ];
__device__ float g_bias1[GSZ];
__device__ __nv_bfloat16 g_h1s[(size_t)MROWS*256];   // [row][hi128|lo128]
__device__ __nv_bfloat16 g_BE[GSZ*384];              // [n][384] = wh|wh|wl
__device__ float g_xp1[(size_t)MROWS*GSZ];
__device__ float g_h2[BATCH*HID];

__device__ __forceinline__ ull dup2(float x){ull d;asm("mov.b64 %0,{%1,%1};":"=l"(d):"f"(x));return d;}
__device__ __forceinline__ ull pk2(float x,float y){ull d;asm("mov.b64 %0,{%1,%2};":"=l"(d):"f"(x),"f"(y));return d;}
__device__ __forceinline__ ull fma2(ull a,ull b,ull c){ull d;asm("fma.rn.f32x2 %0,%1,%2,%3;":"=l"(d):"l"(a),"l"(b),"l"(c));return d;}
__device__ __forceinline__ float2 unp(ull v){float2 r;asm("mov.b64 {%0,%1},%2;":"=f"(r.x),"=f"(r.y):"l"(v));return r;}
__device__ __forceinline__ float sigm(float x){return __fdividef(1.0f,1.0f+__expf(-x));}
__device__ __forceinline__ float tanh_f(float x){return __fdividef(2.0f,1.0f+__expf(-2.0f*x))-1.0f;}

// one weight row (2 gate cols) x 8 batch rows -> 8 f32x2 accumulators
#define FMA_ROW(W2V,KIDX) do{ \
    ull w0=dup2((W2V).x), w1=dup2((W2V).y); \
    ulonglong2 vA=*(const ulonglong2*)&v_s[(KIDX)*12]; \
    ulonglong2 vB=*(const ulonglong2*)&v_s[(KIDX)*12+4]; \
    a0=fma2(w0,vA.x,a0); a1=fma2(w0,vA.y,a1); \
    a2=fma2(w0,vB.x,a2); a3=fma2(w0,vB.y,a3); \
    a4=fma2(w1,vA.x,a4); a5=fma2(w1,vA.y,a5); \
    a6=fma2(w1,vB.x,a6); a7=fma2(w1,vB.y,a7); }while(0)

#define MMA(d,a,b0,b1) \
    asm volatile("mma.sync.aligned.m16n8k16.row.col.f32.bf16.bf16.f32 " \
        "{%0,%1,%2,%3},{%4,%5,%6,%7},{%8,%9},{%0,%1,%2,%3};" \
        : "+f"((d)[0]),"+f"((d)[1]),"+f"((d)[2]),"+f"((d)[3]) \
        : "r"((a)[0]),"r"((a)[1]),"r"((a)[2]),"r"((a)[3]),"r"(b0),"r"(b1))

__global__ void prep_kernel(const float* __restrict__ Wih0,const float* __restrict__ Whh0,
                            const float* __restrict__ bih0,const float* __restrict__ bhh0,
                            const float* __restrict__ Wih1,const float* __restrict__ Whh1,
                            const float* __restrict__ bih1,const float* __restrict__ bhh1){
    int i = blockIdx.x*blockDim.x + threadIdx.x;
    const int S0=KP0*GSZ, S1=S0+KP1*GSZ, S2=S1+GSZ, S3=S2+GSZ, S4=S3+GSZ*384;
    if(i<S0){
        int k=i/GSZ, j=i%GSZ; float v=0.f;
        if(k<DIN) v=Wih0[j*DIN+k]; else if(k<DIN+HID) v=Whh0[j*HID+(k-DIN)];
        g_W0T[i]=v;
    }else if(i<S1){
        int i2=i-S0; int k=i2/GSZ, j=i2%GSZ;
        g_W1T[i2]=Whh1[j*HID+k];
    }else if(i<S2){ int j=i-S1; g_bias0[j]=bih0[j]+bhh0[j]; }
    else if(i<S3){ int j=i-S2; g_bias1[j]=bih1[j]+bhh1[j]; }
    else if(i<S4){
        int i2=i-S3; int n=i2/384, kp=i2%384, k=kp&127;
        float w=Wih1[n*HID+k];
        __nv_bfloat16 hi=__float2bfloat16(w);
        g_BE[i2] = (kp<256)? hi : __float2bfloat16(w-__bfloat162float(hi));
    }
}

// xp1 = h1(split bf16) @ W_ih1^T + b1 via mma.sync; A and B tiles both in smem.
__global__ void __launch_bounds__(256,1) xp_gemm_kernel(){
    extern __shared__ __nv_bfloat16 sh[];
    __nv_bfloat16* As = sh;                // [128][AS]
    __nv_bfloat16* Bs = sh + 128*AS;       // [128][BSTR]
    int tid=threadIdx.x, wid=tid>>5, lane=tid&31;
    int g=lane>>2, t=lane&3;
    size_t mbase=(size_t)blockIdx.x*128;
    int ny=blockIdx.y;
    {
        const float4* src=(const float4*)(g_h1s + mbase*256);
        for(int i=tid;i<4096;i+=256){
            int r=i>>5, c=i&31;
            *(float4*)(As + r*AS + c*8)=src[r*32+c];
        }
        const float4* bsrc=(const float4*)(g_BE + (size_t)ny*128*384);
        for(int i=tid;i<6144;i+=256){
            int n=i/48, kq=i%48;
            *(float4*)(Bs + n*BSTR + kq*8)=bsrc[i];
        }
    }
    __syncthreads();
    int nl0=(wid>>2)*64;
    int m0=(wid&3)*32;
    float acc[2][8][4];
#pragma unroll
    for(int mi=0;mi<2;mi++)
#pragma unroll
        for(int ni=0;ni<8;ni++)
#pragma unroll
            for(int q=0;q<4;q++) acc[mi][ni][q]=0.f;
#pragma unroll 1
    for(int kc=0;kc<24;kc++){
        int ks=(kc<8)?kc*16:(kc<16)?(128+(kc-8)*16):((kc-16)*16);
        int kb=kc*16;
        uint32_t a[2][4];
#pragma unroll
        for(int mi=0;mi<2;mi++){
            const __nv_bfloat16* ap=As+(m0+mi*16)*AS+ks;
            a[mi][0]=*(const uint32_t*)(ap+g*AS+2*t);
            a[mi][1]=*(const uint32_t*)(ap+(g+8)*AS+2*t);
            a[mi][2]=*(const uint32_t*)(ap+g*AS+2*t+8);
            a[mi][3]=*(const uint32_t*)(ap+(g+8)*AS+2*t+8);
        }
#pragma unroll
        for(int ni=0;ni<8;ni++){
            const __nv_bfloat16* bp=Bs+(nl0+ni*8+g)*BSTR+kb;
            uint32_t b0=*(const uint32_t*)(bp+2*t);
            uint32_t b1=*(const uint32_t*)(bp+2*t+8);
            MMA(acc[0][ni],a[0],b0,b1);
            MMA(acc[1][ni],a[1],b0,b1);
        }
    }
#pragma unroll
    for(int mi=0;mi<2;mi++)
#pragma unroll
        for(int ni=0;ni<8;ni++){
            int col=ny*128+nl0+ni*8+2*t;
            float bx=g_bias1[col], by=g_bias1[col+1];
            size_t r0=mbase+m0+mi*16+g;
            *(float2*)&g_xp1[r0*GSZ+col]     = make_float2(acc[mi][ni][0]+bx, acc[mi][ni][1]+by);
            *(float2*)&g_xp1[(r0+8)*GSZ+col] = make_float2(acc[mi][ni][2]+bx, acc[mi][ni][3]+by);
        }
}

// fused LSTM scan: 256 threads, 2 gate cols/thread, fully weight-resident,
// smem-row / register-row FMA interleaved (2:1 L0, 3:1 L1) for LDS latency hiding.
template <int LAYER>
__global__ void __launch_bounds__(256,1) lstm_kernel(const float* __restrict__ x){
    constexpr int KP=(LAYER==0)?KP0:KP1;
    constexpr int PRM=KP-SRR;                 // 48 / 32
    constexpr int SPG=SRR/PRM;                // smem rows per group: 2 / 3
    constexpr int KOFF=(LAYER==0)?DIN:0;
    const float* __restrict__ WT=(LAYER==0)?g_W0T:g_W1T;

    extern __shared__ float smem[];
    float* w_s=smem;                 // SRR*512
    float* v_s=w_s+SRR*GSZ;          // KP*12
    float* g_s=v_s+KP*12;            // 8*512

    const int tid=threadIdx.x;
    const int b0=blockIdx.x*BT;
    const int j0=2*tid;
    {
        const float2* src=(const float2*)WT;
        float2* dst=(float2*)w_s;
        for(int i=tid;i<SRR*GSZ/2;i+=256) dst[i]=src[i];
    }
    for(int i=tid;i<KP*12;i+=256) v_s[i]=0.f;

    float2 pbuf[PRM];
#pragma unroll
    for(int i=0;i<PRM;i++) pbuf[i]=*(const float2*)&WT[(SRR+i)*GSZ+j0];

    ull bxd=0, byd=0;
    if(LAYER==0){
        float2 bj=*(const float2*)&g_bias0[j0];
        bxd=dup2(bj.x); byd=dup2(bj.y);
    }
    const int ub=tid>>5, um=tid&31;
    float c_r[4]={0.f,0.f,0.f,0.f};

    for(int t=0;t<TLEN;t++){
        float xstage=0.f; float2 xpr[8];
        int st_r=0, st_d=0;
        if(LAYER==0){
            if(tid<96){ st_r=tid/12; st_d=tid%12;
                xstage=x[(((size_t)(b0+st_r))*TLEN+t)*DIN+st_d]; }
        }else{
            const float* xpb=g_xp1+(((size_t)t)*BATCH+b0)*GSZ+j0;
#pragma unroll
            for(int b=0;b<8;b++) xpr[b]=*(const float2*)(xpb+(size_t)b*GSZ);
        }
        if(t>0){
#pragma unroll
            for(int q=0;q<4;q++){
                int m=um+32*q;
                float iv=sigm(g_s[ub*GSZ+m]);
                float fv=sigm(g_s[ub*GSZ+128+m]);
                float gv=tanh_f(g_s[ub*GSZ+256+m]);
                float ov=sigm(g_s[ub*GSZ+384+m]);
                float c=fv*c_r[q]+iv*gv; c_r[q]=c;
                float h=ov*tanh_f(c);
                v_s[(KOFF+m)*12+ub]=h;
                if(LAYER==0){
                    size_t row=((size_t)(t-1))*BATCH+b0+ub;
                    __nv_bfloat16 hb=__float2bfloat16(h);
                    g_h1s[row*256+m]=hb;
                    g_h1s[row*256+128+m]=__float2bfloat16(h-__bfloat162float(hb));
                }
            }
        }
        if(LAYER==0){ if(tid<96) v_s[st_d*12+st_r]=xstage; }
        __syncthreads();

        ull a0,a1,a2,a3,a4,a5,a6,a7;
        if(LAYER==0){ a0=bxd;a1=bxd;a2=bxd;a3=bxd; a4=byd;a5=byd;a6=byd;a7=byd; }
        else{
            a0=pk2(xpr[0].x,xpr[1].x); a1=pk2(xpr[2].x,xpr[3].x);
            a2=pk2(xpr[4].x,xpr[5].x); a3=pk2(xpr[6].x,xpr[7].x);
            a4=pk2(xpr[0].y,xpr[1].y); a5=pk2(xpr[2].y,xpr[3].y);
            a6=pk2(xpr[4].y,xpr[5].y); a7=pk2(xpr[6].y,xpr[7].y);
        }
        // interleaved GEMV: SPG smem rows then 1 register row per group.
        // Register-row FMAs (no LDS) overlap the next smem rows' LDS latency.
#pragma unroll 4
        for(int g=0;g<PRM;g++){
#pragma unroll
            for(int s=0;s<SPG;s++){
                int k=g*SPG+s;
                float2 w=*(const float2*)&w_s[k*GSZ+j0];
                FMA_ROW(w,k);
            }
            FMA_ROW(pbuf[g],SRR+g);
        }
        {
            ull ac0[4]={a0,a1,a2,a3}, ac1[4]={a4,a5,a6,a7};
#pragma unroll
            for(int p=0;p<4;p++){
                float2 u0=unp(ac0[p]), u1=unp(ac1[p]);
                *(float2*)&g_s[(2*p)*GSZ+j0]  =make_float2(u0.x,u1.x);
                *(float2*)&g_s[(2*p+1)*GSZ+j0]=make_float2(u0.y,u1.y);
            }
        }
        __syncthreads();
    }
#pragma unroll
    for(int q=0;q<4;q++){
        int m=um+32*q;
        float iv=sigm(g_s[ub*GSZ+m]);
        float fv=sigm(g_s[ub*GSZ+128+m]);
        float gv=tanh_f(g_s[ub*GSZ+256+m]);
        float ov=sigm(g_s[ub*GSZ+384+m]);
        float c=fv*c_r[q]+iv*gv;
        float h=ov*tanh_f(c);
        if(LAYER==0){
            size_t row=((size_t)(TLEN-1))*BATCH+b0+ub;
            __nv_bfloat16 hb=__float2bfloat16(h);
            g_h1s[row*256+m]=hb;
            g_h1s[row*256+128+m]=__float2bfloat16(h-__bfloat162float(hb));
        }else g_h2[(b0+ub)*HID+m]=h;
    }
}

__global__ void head_kernel(const float* __restrict__ W1,const float* __restrict__ b1,
                            const float* __restrict__ W2,const float* __restrict__ b2,
                            const float* __restrict__ W3,const float* __restrict__ b3,
                            float* __restrict__ out){
    __shared__ float hrow[HID]; __shared__ float z1[64]; __shared__ float z2[32];
    int b=blockIdx.x, tid=threadIdx.x;
    hrow[tid]=g_h2[b*HID+tid];
    hrow[tid+64]=g_h2[b*HID+tid+64];
    __syncthreads();
    {
        float s=b1[tid];
        const float* w=&W1[tid*HID];
#pragma unroll 8
        for(int k=0;k<HID;k++) s+=w[k]*hrow[k];
        z1[tid]=fmaxf(s,0.f);
    }
    __syncthreads();
    if(tid<32){
        float s=b2[tid];
        const float* w=&W2[tid*64];
#pragma unroll 8
        for(int k=0;k<64;k++) s+=w[k]*z1[k];
        z2[tid]=fmaxf(s,0.f);
    }
    __syncthreads();
    if(tid<2){
        float s=b3[tid];
        const float* w=&W3[tid*32];
#pragma unroll
        for(int k=0;k<32;k++) s+=w[k]*z2[k];
        out[b*2+tid]=s;
    }
}

extern "C" void kernel_launch(void* const* d_in, const int* in_sizes, int n_in,
                              void* d_out, int out_size){
    const float* x   =(const float*)d_in[0];
    const float* Wih0=(const float*)d_in[1];
    const float* Whh0=(const float*)d_in[2];
    const float* bih0=(const float*)d_in[3];
    const float* bhh0=(const float*)d_in[4];
    const float* Wih1=(const float*)d_in[5];
    const float* Whh1=(const float*)d_in[6];
    const float* bih1=(const float*)d_in[7];
    const float* bhh1=(const float*)d_in[8];
    const float* W1=(const float*)d_in[9];
    const float* b1=(const float*)d_in[10];
    const float* W2=(const float*)d_in[11];
    const float* b2=(const float*)d_in[12];
    const float* W3=(const float*)d_in[13];
    const float* b3=(const float*)d_in[14];
    float* out=(float*)d_out;

    const int smem0=(SRR*GSZ+KP0*12+8*GSZ)*4;    // 219,904 B
    const int smem1=(SRR*GSZ+KP1*12+8*GSZ)*4;    // 219,136 B
    const int smemg=(128*AS+128*BSTR)*2;          // 167,936 B
    cudaFuncSetAttribute((const void*)lstm_kernel<0>,cudaFuncAttributeMaxDynamicSharedMemorySize,smem0);
    cudaFuncSetAttribute((const void*)lstm_kernel<1>,cudaFuncAttributeMaxDynamicSharedMemorySize,smem1);
    cudaFuncSetAttribute((const void*)xp_gemm_kernel,cudaFuncAttributeMaxDynamicSharedMemorySize,smemg);

    int tot=(KP0+KP1)*GSZ+2*GSZ+GSZ*384;
    prep_kernel<<<(tot+255)/256,256>>>(Wih0,Whh0,bih0,bhh0,Wih1,Whh1,bih1,bhh1);
    lstm_kernel<0><<<NBLK,256,smem0>>>(x);
    xp_gemm_kernel<<<dim3(MROWS/128,4),256,smemg>>>();
    lstm_kernel<1><<<NBLK,256,smem1>>>(nullptr);
    head_kernel<<<BATCH,64>>>(W1,b1,W2,b2,W3,b3,out);
}